// round 1
// baseline (speedup 1.0000x reference)
#include <cuda_runtime.h>

typedef unsigned long long u64;
#define DEV __device__ __forceinline__

// ---------- packed fp32x2 helpers (Blackwell FFMA2: 2x fp32 FMA rate) ----------
DEV u64 pack2(float lo, float hi) {
    u64 r; asm("mov.b64 %0, {%1,%2};" : "=l"(r) : "f"(lo), "f"(hi)); return r;
}
DEV void unpack2(u64 v, float& lo, float& hi) {
    asm("mov.b64 {%0,%1}, %2;" : "=f"(lo), "=f"(hi) : "l"(v));
}
DEV u64 ffma2(u64 a, u64 b, u64 c) {
    u64 d; asm("fma.rn.f32x2 %0, %1, %2, %3;" : "=l"(d) : "l"(a), "l"(b), "l"(c)); return d;
}

#define BATCH 4
#define HW    4096
#define CDIM  512
#define CK    64
#define MROWS (BATCH*HW)

// ---------- device scratch (no allocations allowed) ----------
__device__ __align__(128) float g_wbc[CDIM * 128];              // [512][128] packed [Wb|Wc]
__device__ __align__(128) float g_bc[(size_t)MROWS * 128];      // [16384][128]: b cols 0..63, c cols 64..127
__device__ __align__(128) float g_d[(size_t)MROWS * CDIM];      // [16384][512]
__device__ float g_m[MROWS];
__device__ float g_linv[MROWS];

// ---------- pack Wb|Wc side by side ----------
__global__ void pack_wbc(const float* __restrict__ Wb, const float* __restrict__ Wc) {
    int i = blockIdx.x * 256 + threadIdx.x;   // over 512*64
    if (i < CDIM * CK) {
        int k = i / CK, n = i % CK;
        g_wbc[k * 128 + n]      = Wb[i];
        g_wbc[k * 128 + 64 + n] = Wc[i];
    }
}

// ---------- projection GEMM: Y[M,N] = X[M,512] @ W[512,N] ----------
// BM=128, BN=128, BK=8, 256 threads, 8x8 micro-tile, f32x2 pairs along N.
__global__ void __launch_bounds__(256) proj_gemm(const float* __restrict__ X,
                                                 const float* __restrict__ Wext,
                                                 float* __restrict__ Y,
                                                 int N, int use_packed) {
    __shared__ float As[8][132];   // [k][m], padded
    __shared__ float Bs[8][128];   // [k][n]
    const float* W = use_packed ? g_wbc : Wext;

    int tid = threadIdx.x;
    int bm = blockIdx.x * 128;
    int bn = blockIdx.y * 128;
    int tx = tid & 15, ty = tid >> 4;
    int lr = tid >> 1, lc = (tid & 1) * 4;     // X tile load
    int wr = tid >> 5, wc = (tid & 31) * 4;    // W tile load

    u64 acc[8][4];
#pragma unroll
    for (int i = 0; i < 8; i++)
#pragma unroll
        for (int j = 0; j < 4; j++) acc[i][j] = 0ull;

    for (int kk = 0; kk < CDIM; kk += 8) {
        float4 xv = *(const float4*)(X + (size_t)(bm + lr) * CDIM + kk + lc);
        As[lc + 0][lr] = xv.x; As[lc + 1][lr] = xv.y;
        As[lc + 2][lr] = xv.z; As[lc + 3][lr] = xv.w;
        *(float4*)(&Bs[wr][wc]) = *(const float4*)(W + (size_t)(kk + wr) * N + bn + wc);
        __syncthreads();
#pragma unroll
        for (int k = 0; k < 8; k++) {
            float4 a0 = *(const float4*)(&As[k][ty * 8]);
            float4 a1 = *(const float4*)(&As[k][ty * 8 + 4]);
            float4 b0 = *(const float4*)(&Bs[k][tx * 4]);
            float4 b1 = *(const float4*)(&Bs[k][64 + tx * 4]);
            u64 bp0 = pack2(b0.x, b0.y), bp1 = pack2(b0.z, b0.w);
            u64 bp2 = pack2(b1.x, b1.y), bp3 = pack2(b1.z, b1.w);
            float am[8] = {a0.x, a0.y, a0.z, a0.w, a1.x, a1.y, a1.z, a1.w};
#pragma unroll
            for (int i = 0; i < 8; i++) {
                u64 ap = pack2(am[i], am[i]);
                acc[i][0] = ffma2(ap, bp0, acc[i][0]);
                acc[i][1] = ffma2(ap, bp1, acc[i][1]);
                acc[i][2] = ffma2(ap, bp2, acc[i][2]);
                acc[i][3] = ffma2(ap, bp3, acc[i][3]);
            }
        }
        __syncthreads();
    }
#pragma unroll
    for (int i = 0; i < 8; i++) {
        float o0, o1, o2, o3;
        unpack2(acc[i][0], o0, o1); unpack2(acc[i][1], o2, o3);
        *(float4*)(Y + (size_t)(bm + ty * 8 + i) * N + bn + tx * 4) = make_float4(o0, o1, o2, o3);
        unpack2(acc[i][2], o0, o1); unpack2(acc[i][3], o2, o3);
        *(float4*)(Y + (size_t)(bm + ty * 8 + i) * N + bn + 64 + tx * 4) = make_float4(o0, o1, o2, o3);
    }
}

// ---------- pass 1: per-query softmax stats (running max m, sum l) ----------
// Tq=64, Tk=64, 128 threads, micro 4q x 8k per thread, stats reduced via shfl in 8-lane groups.
__global__ void __launch_bounds__(128) stats_kernel() {
    __shared__ float Cs[64][66];   // c tile [q][e], padded
    __shared__ float Bts[64][64];  // b tile transposed [e][k]

    int tid = threadIdx.x;
    int bz = blockIdx.y;
    int qb = blockIdx.x * 64;
    int rowbase = bz * HW;

    // load Cs (queries for this block, fixed)
    for (int i = tid; i < 64 * 16; i += 128) {
        int q = i >> 4, e4 = (i & 15) << 2;
        float4 v = *(const float4*)(g_bc + (size_t)(rowbase + qb + q) * 128 + 64 + e4);
        Cs[q][e4 + 0] = v.x; Cs[q][e4 + 1] = v.y; Cs[q][e4 + 2] = v.z; Cs[q][e4 + 3] = v.w;
    }

    int qg = tid >> 3;          // 0..15
    int q0 = qg << 2;           // 4 query rows per thread
    int tx = tid & 7;           // k cols: {tx*4..+3} U {32+tx*4..+3}

    float m[4] = {-1e30f, -1e30f, -1e30f, -1e30f};
    float l[4] = {0.f, 0.f, 0.f, 0.f};

    for (int kt = 0; kt < HW; kt += 64) {
        __syncthreads();   // protect Bts from previous tile's reads (also orders Cs load)
        {
            int k = tid & 63;
            int eh = (tid >> 6) * 32;
            const float* src = g_bc + (size_t)(rowbase + kt + k) * 128 + eh;
#pragma unroll
            for (int j = 0; j < 8; j++) {
                float4 v = *(const float4*)(src + j * 4);
                Bts[eh + j * 4 + 0][k] = v.x; Bts[eh + j * 4 + 1][k] = v.y;
                Bts[eh + j * 4 + 2][k] = v.z; Bts[eh + j * 4 + 3][k] = v.w;
            }
        }
        __syncthreads();

        u64 s2[4][4];
#pragma unroll
        for (int i = 0; i < 4; i++)
#pragma unroll
            for (int c = 0; c < 4; c++) s2[i][c] = 0ull;

#pragma unroll 4
        for (int e = 0; e < 64; e++) {
            float4 bA = *(const float4*)(&Bts[e][tx * 4]);
            float4 bB = *(const float4*)(&Bts[e][32 + tx * 4]);
            u64 b0 = pack2(bA.x, bA.y), b1 = pack2(bA.z, bA.w);
            u64 b2 = pack2(bB.x, bB.y), b3 = pack2(bB.z, bB.w);
#pragma unroll
            for (int i = 0; i < 4; i++) {
                float cv = Cs[q0 + i][e];
                u64 cp = pack2(cv, cv);
                s2[i][0] = ffma2(cp, b0, s2[i][0]);
                s2[i][1] = ffma2(cp, b1, s2[i][1]);
                s2[i][2] = ffma2(cp, b2, s2[i][2]);
                s2[i][3] = ffma2(cp, b3, s2[i][3]);
            }
        }

#pragma unroll
        for (int i = 0; i < 4; i++) {
            float s[8];
            unpack2(s2[i][0], s[0], s[1]); unpack2(s2[i][1], s[2], s[3]);
            unpack2(s2[i][2], s[4], s[5]); unpack2(s2[i][3], s[6], s[7]);
            float tm = s[0];
#pragma unroll
            for (int j = 1; j < 8; j++) tm = fmaxf(tm, s[j]);
            tm = fmaxf(tm, __shfl_xor_sync(0xffffffffu, tm, 1));
            tm = fmaxf(tm, __shfl_xor_sync(0xffffffffu, tm, 2));
            tm = fmaxf(tm, __shfl_xor_sync(0xffffffffu, tm, 4));
            float nm = fmaxf(m[i], tm);
            float ts = 0.f;
#pragma unroll
            for (int j = 0; j < 8; j++) ts += __expf(s[j] - nm);
            ts += __shfl_xor_sync(0xffffffffu, ts, 1);
            ts += __shfl_xor_sync(0xffffffffu, ts, 2);
            ts += __shfl_xor_sync(0xffffffffu, ts, 4);
            l[i] = l[i] * __expf(m[i] - nm) + ts;
            m[i] = nm;
        }
    }

    if (tx == 0) {
#pragma unroll
        for (int i = 0; i < 4; i++) {
            g_m[rowbase + qb + q0 + i] = m[i];
            g_linv[rowbase + qb + q0 + i] = 1.0f / l[i];
        }
    }
}

// ---------- pass 2: out = softmax(c b^T) @ d, epilogue gamma*out + x ----------
// Tq=32, Tk=256, 256 threads. S-phase: 4q x 8k micro. PV-phase: 4q x 16f micro (f interleaved).
// Dynamic smem: Cs 32*64 + Bts 64*256 + Ps 32*256 + Ds 32*512 + stats 64.
#define SMEM_ATTN ((32*64 + 64*256 + 32*256 + 32*512 + 64) * sizeof(float))

__global__ void __launch_bounds__(256) attn_out_kernel(const float* __restrict__ x,
                                                       const float* __restrict__ gamma,
                                                       float* __restrict__ out) {
    extern __shared__ float sm[];
    float* Cs   = sm;                  // [32][64]
    float* Bts  = Cs + 32 * 64;        // [64][256] transposed b tile
    float* Ps   = Bts + 64 * 256;      // [32][256]
    float* Ds   = Ps + 32 * 256;       // [32][512]
    float* Mrow = Ds + 32 * 512;       // [32]
    float* Lrow = Mrow + 32;           // [32]

    int tid = threadIdx.x;
    int bz = blockIdx.y;
    int qb = blockIdx.x * 32;
    int rowbase = bz * HW;

    // load Cs
    for (int i = tid; i < 32 * 16; i += 256) {
        int q = i >> 4, e4 = (i & 15) << 2;
        *(float4*)(Cs + q * 64 + e4) =
            *(const float4*)(g_bc + (size_t)(rowbase + qb + q) * 128 + 64 + e4);
    }
    if (tid < 32) {
        Mrow[tid] = g_m[rowbase + qb + tid];
        Lrow[tid] = g_linv[rowbase + qb + tid];
    }

    int tidq = tid >> 5;          // warp id = q-group (4 rows)
    int q0 = tidq * 4;
    int tidf = tid & 31;          // f cols: tidf*4 + 128*j, j=0..3 ; S-phase k cols: tidf*4 (+128)
    int f0 = tidf * 4;

    u64 acc[4][8];
#pragma unroll
    for (int i = 0; i < 4; i++)
#pragma unroll
        for (int j = 0; j < 8; j++) acc[i][j] = 0ull;

    for (int kt = 0; kt < HW; kt += 256) {
        // ---- load Bts[64][256] (transposed) ----
        {
            int k = tid;
            const float* src = g_bc + (size_t)(rowbase + kt + k) * 128;
#pragma unroll
            for (int j = 0; j < 16; j++) {
                float4 v = *(const float4*)(src + j * 4);
                Bts[(j * 4 + 0) * 256 + k] = v.x; Bts[(j * 4 + 1) * 256 + k] = v.y;
                Bts[(j * 4 + 2) * 256 + k] = v.z; Bts[(j * 4 + 3) * 256 + k] = v.w;
            }
        }
        __syncthreads();

        // ---- S phase: s = c . b, then p = exp(s-m)/l into Ps ----
        u64 s2[4][4];
#pragma unroll
        for (int i = 0; i < 4; i++)
#pragma unroll
            for (int c = 0; c < 4; c++) s2[i][c] = 0ull;

#pragma unroll 4
        for (int e = 0; e < 64; e++) {
            float4 bA = *(const float4*)(&Bts[e * 256 + f0]);
            float4 bB = *(const float4*)(&Bts[e * 256 + 128 + f0]);
            u64 b0 = pack2(bA.x, bA.y), b1 = pack2(bA.z, bA.w);
            u64 b2 = pack2(bB.x, bB.y), b3 = pack2(bB.z, bB.w);
#pragma unroll
            for (int i = 0; i < 4; i++) {
                float cv = Cs[(q0 + i) * 64 + e];
                u64 cp = pack2(cv, cv);
                s2[i][0] = ffma2(cp, b0, s2[i][0]);
                s2[i][1] = ffma2(cp, b1, s2[i][1]);
                s2[i][2] = ffma2(cp, b2, s2[i][2]);
                s2[i][3] = ffma2(cp, b3, s2[i][3]);
            }
        }
#pragma unroll
        for (int i = 0; i < 4; i++) {
            float s[8];
            unpack2(s2[i][0], s[0], s[1]); unpack2(s2[i][1], s[2], s[3]);
            unpack2(s2[i][2], s[4], s[5]); unpack2(s2[i][3], s[6], s[7]);
            float mi = Mrow[q0 + i], li = Lrow[q0 + i];
            float* prow = Ps + (q0 + i) * 256;
#pragma unroll
            for (int j = 0; j < 4; j++) prow[f0 + j]       = __expf(s[j] - mi) * li;
#pragma unroll
            for (int j = 0; j < 4; j++) prow[128 + f0 + j] = __expf(s[4 + j] - mi) * li;
        }
        __syncthreads();

        // ---- PV phase: O += p @ d, 8 sub-tiles of 32 keys ----
        for (int ks = 0; ks < 8; ks++) {
            {
                int n = tid >> 3;
                const float* src = g_d + (size_t)(rowbase + kt + ks * 32 + n) * CDIM + (tid & 7) * 4;
                float* dst = Ds + n * CDIM + (tid & 7) * 4;
#pragma unroll
                for (int j = 0; j < 16; j++)
                    *(float4*)(dst + j * 32) = *(const float4*)(src + j * 32);
            }
            __syncthreads();

#pragma unroll 2
            for (int n = 0; n < 32; n++) {
                u64 dp[8];
#pragma unroll
                for (int j = 0; j < 4; j++) {
                    float4 dv = *(const float4*)(Ds + n * CDIM + f0 + 128 * j);
                    dp[2 * j]     = pack2(dv.x, dv.y);
                    dp[2 * j + 1] = pack2(dv.z, dv.w);
                }
#pragma unroll
                for (int i = 0; i < 4; i++) {
                    float pv = Ps[(q0 + i) * 256 + ks * 32 + n];
                    u64 pp = pack2(pv, pv);
#pragma unroll
                    for (int j = 0; j < 8; j++) acc[i][j] = ffma2(pp, dp[j], acc[i][j]);
                }
            }
            __syncthreads();
        }
    }

    // ---- epilogue: gamma*O + x ----
    float g = *gamma;
#pragma unroll
    for (int i = 0; i < 4; i++) {
        size_t row = (size_t)(rowbase + qb + q0 + i);
#pragma unroll
        for (int j = 0; j < 4; j++) {
            float o0, o1, o2, o3;
            unpack2(acc[i][2 * j], o0, o1); unpack2(acc[i][2 * j + 1], o2, o3);
            int col = f0 + 128 * j;
            float4 xv = *(const float4*)(x + row * CDIM + col);
            float4 ov = make_float4(g * o0 + xv.x, g * o1 + xv.y,
                                    g * o2 + xv.z, g * o3 + xv.w);
            *(float4*)(out + row * CDIM + col) = ov;
        }
    }
}

// ---------- launch ----------
extern "C" void kernel_launch(void* const* d_in, const int* in_sizes, int n_in,
                              void* d_out, int out_size) {
    const float* x     = (const float*)d_in[0];
    const float* Wb    = (const float*)d_in[1];
    const float* Wc    = (const float*)d_in[2];
    const float* Wd    = (const float*)d_in[3];
    const float* gamma = (const float*)d_in[4];
    float* out = (float*)d_out;

    float* gbc_ptr; float* gd_ptr;
    cudaGetSymbolAddress((void**)&gbc_ptr, g_bc);
    cudaGetSymbolAddress((void**)&gd_ptr, g_d);

    pack_wbc<<<128, 256>>>(Wb, Wc);
    proj_gemm<<<dim3(MROWS / 128, 1), 256>>>(x, nullptr, gbc_ptr, 128, 1);
    proj_gemm<<<dim3(MROWS / 128, 4), 256>>>(x, Wd, gd_ptr, 512, 0);
    stats_kernel<<<dim3(HW / 64, BATCH), 128>>>();

    cudaFuncSetAttribute(attn_out_kernel, cudaFuncAttributeMaxDynamicSharedMemorySize,
                         (int)SMEM_ATTN);
    attn_out_kernel<<<dim3(HW / 32, BATCH), 256, SMEM_ATTN>>>(x, gamma, out);
}

// round 2
// speedup vs baseline: 1.8022x; 1.8022x over previous
#include <cuda_runtime.h>

typedef unsigned long long u64;
typedef unsigned int uint32;
#define DEV __device__ __forceinline__

// ---------- packed fp32x2 helpers (fp32 path for b,c projections) ----------
DEV u64 pack2(float lo, float hi) {
    u64 r; asm("mov.b64 %0, {%1,%2};" : "=l"(r) : "f"(lo), "f"(hi)); return r;
}
DEV void unpack2(u64 v, float& lo, float& hi) {
    asm("mov.b64 {%0,%1}, %2;" : "=f"(lo), "=f"(hi) : "l"(v));
}
DEV u64 ffma2(u64 a, u64 b, u64 c) {
    u64 d; asm("fma.rn.f32x2 %0, %1, %2, %3;" : "=l"(d) : "l"(a), "l"(b), "l"(c)); return d;
}

// ---------- tf32 mma helpers ----------
DEV uint32 f2tf(float f) {
    uint32 u; asm("cvt.rna.tf32.f32 %0, %1;" : "=r"(u) : "f"(f)); return u;
}
DEV void mma8(float4& d, uint32 a0, uint32 a1, uint32 a2, uint32 a3,
              uint32 b0, uint32 b1) {
    asm volatile("mma.sync.aligned.m16n8k8.row.col.f32.tf32.tf32.f32 "
                 "{%0,%1,%2,%3}, {%4,%5,%6,%7}, {%8,%9}, {%0,%1,%2,%3};"
                 : "+f"(d.x), "+f"(d.y), "+f"(d.z), "+f"(d.w)
                 : "r"(a0), "r"(a1), "r"(a2), "r"(a3), "r"(b0), "r"(b1));
}

#define BATCH 4
#define HW    4096
#define CDIM  512
#define CK    64
#define MROWS (BATCH*HW)

// ---------- device scratch ----------
__device__ __align__(128) float  g_wbc[CDIM * 128];                 // packed [Wb|Wc]
__device__ __align__(128) float  g_bc[(size_t)MROWS * 128];         // fp32 [b|c]
__device__ __align__(128) uint32 g_bcs[(size_t)MROWS * 256];        // tf32 [bh|bl|ch|cl]
__device__ __align__(128) uint32 g_d[(size_t)MROWS * CDIM];         // tf32 d

// ---------- pack Wb|Wc side by side ----------
__global__ void pack_wbc(const float* __restrict__ Wb, const float* __restrict__ Wc) {
    int i = blockIdx.x * 256 + threadIdx.x;
    if (i < CDIM * CK) {
        int k = i / CK, n = i % CK;
        g_wbc[k * 128 + n]      = Wb[i];
        g_wbc[k * 128 + 64 + n] = Wc[i];
    }
}

// ---------- fp32 projection GEMM for b,c (exactness needed for softmax) ----------
__global__ void __launch_bounds__(256) proj_gemm(const float* __restrict__ X,
                                                 float* __restrict__ Y, int N) {
    __shared__ float As[8][132];
    __shared__ float Bs[8][128];
    const float* W = g_wbc;

    int tid = threadIdx.x;
    int bm = blockIdx.x * 128;
    int bn = blockIdx.y * 128;
    int tx = tid & 15, ty = tid >> 4;
    int lr = tid >> 1, lc = (tid & 1) * 4;
    int wr = tid >> 5, wc = (tid & 31) * 4;

    u64 acc[8][4];
#pragma unroll
    for (int i = 0; i < 8; i++)
#pragma unroll
        for (int j = 0; j < 4; j++) acc[i][j] = 0ull;

    for (int kk = 0; kk < CDIM; kk += 8) {
        float4 xv = *(const float4*)(X + (size_t)(bm + lr) * CDIM + kk + lc);
        As[lc + 0][lr] = xv.x; As[lc + 1][lr] = xv.y;
        As[lc + 2][lr] = xv.z; As[lc + 3][lr] = xv.w;
        *(float4*)(&Bs[wr][wc]) = *(const float4*)(W + (size_t)(kk + wr) * N + bn + wc);
        __syncthreads();
#pragma unroll
        for (int k = 0; k < 8; k++) {
            float4 a0 = *(const float4*)(&As[k][ty * 8]);
            float4 a1 = *(const float4*)(&As[k][ty * 8 + 4]);
            float4 b0 = *(const float4*)(&Bs[k][tx * 4]);
            float4 b1 = *(const float4*)(&Bs[k][64 + tx * 4]);
            u64 bp0 = pack2(b0.x, b0.y), bp1 = pack2(b0.z, b0.w);
            u64 bp2 = pack2(b1.x, b1.y), bp3 = pack2(b1.z, b1.w);
            float am[8] = {a0.x, a0.y, a0.z, a0.w, a1.x, a1.y, a1.z, a1.w};
#pragma unroll
            for (int i = 0; i < 8; i++) {
                u64 ap = pack2(am[i], am[i]);
                acc[i][0] = ffma2(ap, bp0, acc[i][0]);
                acc[i][1] = ffma2(ap, bp1, acc[i][1]);
                acc[i][2] = ffma2(ap, bp2, acc[i][2]);
                acc[i][3] = ffma2(ap, bp3, acc[i][3]);
            }
        }
        __syncthreads();
    }
#pragma unroll
    for (int i = 0; i < 8; i++) {
        float o0, o1, o2, o3;
        unpack2(acc[i][0], o0, o1); unpack2(acc[i][1], o2, o3);
        *(float4*)(Y + (size_t)(bm + ty * 8 + i) * N + bn + tx * 4) = make_float4(o0, o1, o2, o3);
        unpack2(acc[i][2], o0, o1); unpack2(acc[i][3], o2, o3);
        *(float4*)(Y + (size_t)(bm + ty * 8 + i) * N + bn + 64 + tx * 4) = make_float4(o0, o1, o2, o3);
    }
}

// ---------- split fp32 b,c into (hi,lo) tf32 pairs ----------
__global__ void convert_bc() {
    int i = blockIdx.x * 256 + threadIdx.x;          // over MROWS*128
    if (i < MROWS * 128) {
        float v = g_bc[i];
        int r = i >> 7, c = i & 127;
        uint32 h = f2tf(v);
        float hf = __uint_as_float(h);
        uint32 l = f2tf(v - hf);
        int bh = (c < 64) ? c : (c + 64);            // [bh|bl|ch|cl]
        g_bcs[(size_t)r * 256 + bh]      = h;
        g_bcs[(size_t)r * 256 + bh + 64] = l;
    }
}

// ---------- tf32 tensor-core projection for d: g_d = tf32(X @ Wd) ----------
__global__ void __launch_bounds__(256) dproj(const float* __restrict__ X,
                                             const float* __restrict__ Wd) {
    __shared__ uint32 Xs[128 * 20];   // [m][k], stride 20 (conflict-free frags)
    __shared__ uint32 Wt[128 * 17];   // [n][k], stride 17

    int tid = threadIdx.x;
    int lane = tid & 31, w = tid >> 5;
    int g = lane >> 2, q = lane & 3;
    int bm = blockIdx.x * 128, bn = blockIdx.y * 128;
    int mw = (w & 3) * 32, nw = (w >> 2) * 64;

    float4 acc[2][8];
#pragma unroll
    for (int i = 0; i < 2; i++)
#pragma unroll
        for (int j = 0; j < 8; j++) acc[i][j] = make_float4(0.f, 0.f, 0.f, 0.f);

    for (int kk = 0; kk < CDIM; kk += 16) {
        // load X tile [128m][16k] -> tf32
        {
            int m = tid >> 1;
#pragma unroll
            for (int j = 0; j < 2; j++) {
                int k = (tid & 1) * 8 + j * 4;
                float4 v = *(const float4*)(X + (size_t)(bm + m) * CDIM + kk + k);
                uint4 u = make_uint4(f2tf(v.x), f2tf(v.y), f2tf(v.z), f2tf(v.w));
                *(uint4*)(Xs + m * 20 + k) = u;
            }
        }
        // load W tile transposed [128n][16k] -> tf32
        {
            int k = tid >> 4;
            int n0 = (tid & 15) * 4;
#pragma unroll
            for (int j = 0; j < 2; j++) {
                int n = n0 + j * 64;
                float4 v = *(const float4*)(Wd + (size_t)(kk + k) * CDIM + bn + n);
                Wt[(n + 0) * 17 + k] = f2tf(v.x);
                Wt[(n + 1) * 17 + k] = f2tf(v.y);
                Wt[(n + 2) * 17 + k] = f2tf(v.z);
                Wt[(n + 3) * 17 + k] = f2tf(v.w);
            }
        }
        __syncthreads();
#pragma unroll
        for (int ks = 0; ks < 2; ks++) {
#pragma unroll
            for (int mt = 0; mt < 2; mt++) {
                int ar = (mw + mt * 16 + g) * 20 + ks * 8 + q;
                uint32 a0 = Xs[ar], a1 = Xs[ar + 8 * 20];
                uint32 a2 = Xs[ar + 4], a3 = Xs[ar + 8 * 20 + 4];
#pragma unroll
                for (int nt = 0; nt < 8; nt++) {
                    int br = (nw + nt * 8 + g) * 17 + ks * 8 + q;
                    mma8(acc[mt][nt], a0, a1, a2, a3, Wt[br], Wt[br + 4]);
                }
            }
        }
        __syncthreads();
    }
    // epilogue: store tf32 bit patterns
#pragma unroll
    for (int mt = 0; mt < 2; mt++) {
        int r0 = bm + mw + mt * 16 + g;
#pragma unroll
        for (int nt = 0; nt < 8; nt++) {
            int col = bn + nw + nt * 8 + 2 * q;
            *(uint2*)(g_d + (size_t)r0 * CDIM + col) =
                make_uint2(f2tf(acc[mt][nt].x), f2tf(acc[mt][nt].y));
            *(uint2*)(g_d + (size_t)(r0 + 8) * CDIM + col) =
                make_uint2(f2tf(acc[mt][nt].z), f2tf(acc[mt][nt].w));
        }
    }
}

// ---------- fused flash attention: S (3x tf32) -> online softmax -> PV (tf32) ----------
// Block: 64 q rows, 512 threads (16 warps), k-tile 128.
// smem: Cs[64][132], Bs[128][132], SP[64][132], Ds[512][36], sc[64], linv[64]
#define SMEM_FLASH ((64*132 + 128*132 + 64*132 + 512*36 + 128) * 4)

__global__ void __launch_bounds__(512) flash_kernel(const float* __restrict__ x,
                                                    const float* __restrict__ gamma,
                                                    float* __restrict__ out) {
    extern __shared__ uint32 smu[];
    uint32* Cs = smu;                    // c split: [r][e]=ch, [r][64+e]=cl
    uint32* Bs = Cs + 64 * 132;          // b split per tile
    uint32* SP = Bs + 128 * 132;         // S (fp32) then P (tf32), in place
    uint32* Ds = SP + 64 * 132;          // d chunk transposed [f][key], stride 36
    float*  sc   = (float*)(Ds + 512 * 36);
    float*  linv = sc + 64;
    float*  SPF = (float*)SP;

    const int tid = threadIdx.x;
    const int w = tid >> 5, lane = tid & 31;
    const int g = lane >> 2, q = lane & 3;
    const int qg = w & 3;                // q-group (16 rows) for S and PV
    const int kq = w >> 2;               // k-quarter (S) / f-quarter (PV)
    const int qb = blockIdx.x * 64;
    const int rowbase = blockIdx.y * HW;

    // load Cs once (cols 128..255 of g_bcs = [ch|cl])
    {
        int r = tid >> 3, c4 = tid & 7;
        const uint32* src = g_bcs + (size_t)(rowbase + qb + r) * 256 + 128;
#pragma unroll
        for (int j = 0; j < 4; j++) {
            int c = (c4 + 8 * j) * 4;
            *(uint4*)(Cs + r * 132 + c) = *(const uint4*)(src + c);
        }
    }

    float4 oacc[16];
#pragma unroll
    for (int i = 0; i < 16; i++) oacc[i] = make_float4(0.f, 0.f, 0.f, 0.f);
    float m_run[4] = {-1e30f, -1e30f, -1e30f, -1e30f};
    float l_run[4] = {0.f, 0.f, 0.f, 0.f};

    for (int kt = 0; kt < HW; kt += 128) {
        // ---- load Bs tile [128 keys][bh|bl] ----
        {
            int r = tid >> 2, c4 = tid & 3;
            const uint32* src = g_bcs + (size_t)(rowbase + kt + r) * 256;
#pragma unroll
            for (int j = 0; j < 8; j++) {
                int c = (c4 + 4 * j) * 4;
                *(uint4*)(Bs + r * 132 + c) = *(const uint4*)(src + c);
            }
        }
        __syncthreads();

        // ---- S phase: warp = 16q x 32k, 3x tf32 ----
        float4 sacc[4];
#pragma unroll
        for (int i = 0; i < 4; i++) sacc[i] = make_float4(0.f, 0.f, 0.f, 0.f);
#pragma unroll
        for (int ks = 0; ks < 8; ks++) {
            int ar = (qg * 16 + g) * 132 + ks * 8 + q;
            uint32 ah0 = Cs[ar],          ah1 = Cs[ar + 8 * 132];
            uint32 ah2 = Cs[ar + 4],      ah3 = Cs[ar + 8 * 132 + 4];
            uint32 al0 = Cs[ar + 64],     al1 = Cs[ar + 8 * 132 + 64];
            uint32 al2 = Cs[ar + 68],     al3 = Cs[ar + 8 * 132 + 68];
#pragma unroll
            for (int nt = 0; nt < 4; nt++) {
                int kb = (kq * 32 + nt * 8 + g) * 132 + ks * 8 + q;
                uint32 bh0 = Bs[kb], bh1 = Bs[kb + 4];
                uint32 bl0 = Bs[kb + 64], bl1 = Bs[kb + 68];
                mma8(sacc[nt], ah0, ah1, ah2, ah3, bh0, bh1);
                mma8(sacc[nt], ah0, ah1, ah2, ah3, bl0, bl1);
                mma8(sacc[nt], al0, al1, al2, al3, bh0, bh1);
            }
        }
        // store raw S (fp32) to SP
#pragma unroll
        for (int nt = 0; nt < 4; nt++) {
            int col = kq * 32 + nt * 8 + 2 * q;
            float* p0 = SPF + (qg * 16 + g) * 132 + col;
            *(float2*)p0 = make_float2(sacc[nt].x, sacc[nt].y);
            *(float2*)(p0 + 8 * 132) = make_float2(sacc[nt].z, sacc[nt].w);
        }
        __syncthreads();

        // ---- online softmax: warp w owns rows 4w..4w+3 ----
#pragma unroll
        for (int i = 0; i < 4; i++) {
            int r = 4 * w + i;
            float4 s = *(const float4*)(SPF + r * 132 + lane * 4);
            float tmax = fmaxf(fmaxf(s.x, s.y), fmaxf(s.z, s.w));
#pragma unroll
            for (int off = 16; off > 0; off >>= 1)
                tmax = fmaxf(tmax, __shfl_xor_sync(0xffffffffu, tmax, off));
            float m_new = fmaxf(m_run[i], tmax);
            float p0 = __expf(s.x - m_new), p1 = __expf(s.y - m_new);
            float p2 = __expf(s.z - m_new), p3 = __expf(s.w - m_new);
            float ls = p0 + p1 + p2 + p3;
#pragma unroll
            for (int off = 16; off > 0; off >>= 1)
                ls += __shfl_xor_sync(0xffffffffu, ls, off);
            float scale = __expf(m_run[i] - m_new);
            l_run[i] = l_run[i] * scale + ls;
            m_run[i] = m_new;
            *(uint4*)(SP + r * 132 + lane * 4) =
                make_uint4(f2tf(p0), f2tf(p1), f2tf(p2), f2tf(p3));
            if (lane == 0) sc[r] = scale;
        }
        __syncthreads();

        // ---- rescale O accumulators ----
        {
            float s0 = sc[qg * 16 + g], s1 = sc[qg * 16 + g + 8];
#pragma unroll
            for (int nt = 0; nt < 16; nt++) {
                oacc[nt].x *= s0; oacc[nt].y *= s0;
                oacc[nt].z *= s1; oacc[nt].w *= s1;
            }
        }

        // ---- PV: 4 chunks of 32 keys; warp = 16q x 128f ----
        for (int ks = 0; ks < 4; ks++) {
            {
                int key = tid >> 4;
                int fb = (tid & 15) * 4;
                const uint32* src = g_d + (size_t)(rowbase + kt + ks * 32 + key) * CDIM + fb;
#pragma unroll
                for (int j = 0; j < 8; j++) {
                    uint4 v = *(const uint4*)(src + j * 64);
                    int f = fb + j * 64;
                    Ds[(f + 0) * 36 + key] = v.x;
                    Ds[(f + 1) * 36 + key] = v.y;
                    Ds[(f + 2) * 36 + key] = v.z;
                    Ds[(f + 3) * 36 + key] = v.w;
                }
            }
            __syncthreads();
#pragma unroll
            for (int ksub = 0; ksub < 4; ksub++) {
                int ar = (qg * 16 + g) * 132 + ks * 32 + ksub * 8 + q;
                uint32 a0 = SP[ar], a1 = SP[ar + 8 * 132];
                uint32 a2 = SP[ar + 4], a3 = SP[ar + 8 * 132 + 4];
#pragma unroll
                for (int nt = 0; nt < 16; nt++) {
                    int br = (kq * 128 + nt * 8 + g) * 36 + ksub * 8 + q;
                    mma8(oacc[nt], a0, a1, a2, a3, Ds[br], Ds[br + 4]);
                }
            }
            __syncthreads();
        }
    }

    // ---- epilogue: out = gamma * O / l + x ----
    if (lane == 0) {
#pragma unroll
        for (int i = 0; i < 4; i++) linv[4 * w + i] = 1.0f / l_run[i];
    }
    __syncthreads();
    {
        float li0 = linv[qg * 16 + g], li1 = linv[qg * 16 + g + 8];
        float gam = *gamma;
        size_t r0 = (size_t)(rowbase + qb + qg * 16 + g);
        size_t r1 = r0 + 8;
#pragma unroll
        for (int nt = 0; nt < 16; nt++) {
            int col = kq * 128 + nt * 8 + 2 * q;
            float2 x0 = *(const float2*)(x + r0 * CDIM + col);
            float2 x1 = *(const float2*)(x + r1 * CDIM + col);
            *(float2*)(out + r0 * CDIM + col) =
                make_float2(gam * oacc[nt].x * li0 + x0.x, gam * oacc[nt].y * li0 + x0.y);
            *(float2*)(out + r1 * CDIM + col) =
                make_float2(gam * oacc[nt].z * li1 + x1.x, gam * oacc[nt].w * li1 + x1.y);
        }
    }
}

// ---------- launch ----------
extern "C" void kernel_launch(void* const* d_in, const int* in_sizes, int n_in,
                              void* d_out, int out_size) {
    const float* x     = (const float*)d_in[0];
    const float* Wb    = (const float*)d_in[1];
    const float* Wc    = (const float*)d_in[2];
    const float* Wd    = (const float*)d_in[3];
    const float* gamma = (const float*)d_in[4];
    float* out = (float*)d_out;

    float* gbc_ptr;
    cudaGetSymbolAddress((void**)&gbc_ptr, g_bc);

    pack_wbc<<<128, 256>>>(Wb, Wc);
    proj_gemm<<<dim3(MROWS / 128, 1), 256>>>(x, gbc_ptr, 128);
    convert_bc<<<(MROWS * 128) / 256, 256>>>();
    dproj<<<dim3(MROWS / 128, CDIM / 128), 256>>>(x, Wd);

    cudaFuncSetAttribute(flash_kernel, cudaFuncAttributeMaxDynamicSharedMemorySize,
                         SMEM_FLASH);
    flash_kernel<<<dim3(HW / 64, BATCH), 512, SMEM_FLASH>>>(x, gamma, out);
}

// round 5
// speedup vs baseline: 4.0065x; 2.2232x over previous
#include <cuda_runtime.h>
#include <cuda_fp16.h>

typedef unsigned long long u64;
typedef unsigned int uint32;
#define DEV __device__ __forceinline__

// ---------- packed fp32x2 helpers (b,c projection stays exact fp32) ----------
DEV u64 pack2(float lo, float hi) {
    u64 r; asm("mov.b64 %0, {%1,%2};" : "=l"(r) : "f"(lo), "f"(hi)); return r;
}
DEV void unpack2(u64 v, float& lo, float& hi) {
    asm("mov.b64 {%0,%1}, %2;" : "=f"(lo), "=f"(hi) : "l"(v));
}
DEV u64 ffma2(u64 a, u64 b, u64 c) {
    u64 d; asm("fma.rn.f32x2 %0, %1, %2, %3;" : "=l"(d) : "l"(a), "l"(b), "l"(c)); return d;
}

// ---------- tf32 helpers (dproj) ----------
DEV uint32 f2tf(float f) {
    uint32 u; asm("cvt.rna.tf32.f32 %0, %1;" : "=r"(u) : "f"(f)); return u;
}
DEV void mma8(float4& d, uint32 a0, uint32 a1, uint32 a2, uint32 a3,
              uint32 b0, uint32 b1) {
    asm volatile("mma.sync.aligned.m16n8k8.row.col.f32.tf32.tf32.f32 "
                 "{%0,%1,%2,%3}, {%4,%5,%6,%7}, {%8,%9}, {%0,%1,%2,%3};"
                 : "+f"(d.x), "+f"(d.y), "+f"(d.z), "+f"(d.w)
                 : "r"(a0), "r"(a1), "r"(a2), "r"(a3), "r"(b0), "r"(b1));
}

// ---------- fp16 mma + ldmatrix ----------
DEV void mma16(float4& d, uint32 a0, uint32 a1, uint32 a2, uint32 a3,
               uint32 b0, uint32 b1) {
    asm volatile("mma.sync.aligned.m16n8k16.row.col.f32.f16.f16.f32 "
                 "{%0,%1,%2,%3}, {%4,%5,%6,%7}, {%8,%9}, {%0,%1,%2,%3};"
                 : "+f"(d.x), "+f"(d.y), "+f"(d.z), "+f"(d.w)
                 : "r"(a0), "r"(a1), "r"(a2), "r"(a3), "r"(b0), "r"(b1));
}
DEV void ldsm4(uint32& r0, uint32& r1, uint32& r2, uint32& r3, uint32 addr) {
    asm volatile("ldmatrix.sync.aligned.m8n8.x4.shared.b16 {%0,%1,%2,%3}, [%4];"
                 : "=r"(r0), "=r"(r1), "=r"(r2), "=r"(r3) : "r"(addr));
}
DEV void ldsm2(uint32& r0, uint32& r1, uint32 addr) {
    asm volatile("ldmatrix.sync.aligned.m8n8.x2.shared.b16 {%0,%1}, [%2];"
                 : "=r"(r0), "=r"(r1) : "r"(addr));
}
DEV uint32 smem_u32(const void* p) {
    uint32 a;
    asm("{ .reg .u64 t; cvta.to.shared.u64 t, %1; cvt.u32.u64 %0, t; }"
        : "=r"(a) : "l"(p));
    return a;
}

#define BATCH 4
#define HW    4096
#define CDIM  512
#define CK    64
#define MROWS (BATCH*HW)

// ---------- device scratch ----------
__device__ __align__(128) float  g_wbc[CDIM * 128];                   // packed [Wb|Wc]
__device__ __align__(128) __half g_bch[(size_t)MROWS * 256];          // [row][bh|bl'|ch|cl']
__device__ __align__(128) __half g_dT[(size_t)BATCH * CDIM * HW];     // d^T [batch][f][key]

// ---------- pack Wb|Wc ----------
__global__ void pack_wbc(const float* __restrict__ Wb, const float* __restrict__ Wc) {
    int i = blockIdx.x * 256 + threadIdx.x;
    if (i < CDIM * CK) {
        int k = i / CK, n = i % CK;
        g_wbc[k * 128 + n]      = Wb[i];
        g_wbc[k * 128 + 64 + n] = Wc[i];
    }
}

// ---------- fp32 b,c projection; epilogue emits scaled fp16 splits ----------
__global__ void __launch_bounds__(256) proj_bc(const float* __restrict__ X) {
    __shared__ float As[8][132];
    __shared__ float Bs[8][128];

    int tid = threadIdx.x;
    int bm = blockIdx.x * 128;
    int tx = tid & 15, ty = tid >> 4;
    int lr = tid >> 1, lc = (tid & 1) * 4;
    int wr = tid >> 5, wc = (tid & 31) * 4;

    u64 acc[8][4];
#pragma unroll
    for (int i = 0; i < 8; i++)
#pragma unroll
        for (int j = 0; j < 4; j++) acc[i][j] = 0ull;

    for (int kk = 0; kk < CDIM; kk += 8) {
        float4 xv = *(const float4*)(X + (size_t)(bm + lr) * CDIM + kk + lc);
        As[lc + 0][lr] = xv.x; As[lc + 1][lr] = xv.y;
        As[lc + 2][lr] = xv.z; As[lc + 3][lr] = xv.w;
        *(float4*)(&Bs[wr][wc]) = *(const float4*)(g_wbc + (size_t)(kk + wr) * 128 + wc);
        __syncthreads();
#pragma unroll
        for (int k = 0; k < 8; k++) {
            float4 a0 = *(const float4*)(&As[k][ty * 8]);
            float4 a1 = *(const float4*)(&As[k][ty * 8 + 4]);
            float4 b0 = *(const float4*)(&Bs[k][tx * 4]);
            float4 b1 = *(const float4*)(&Bs[k][64 + tx * 4]);
            u64 bp0 = pack2(b0.x, b0.y), bp1 = pack2(b0.z, b0.w);
            u64 bp2 = pack2(b1.x, b1.y), bp3 = pack2(b1.z, b1.w);
            float am[8] = {a0.x, a0.y, a0.z, a0.w, a1.x, a1.y, a1.z, a1.w};
#pragma unroll
            for (int i = 0; i < 8; i++) {
                u64 ap = pack2(am[i], am[i]);
                acc[i][0] = ffma2(ap, bp0, acc[i][0]);
                acc[i][1] = ffma2(ap, bp1, acc[i][1]);
                acc[i][2] = ffma2(ap, bp2, acc[i][2]);
                acc[i][3] = ffma2(ap, bp3, acc[i][3]);
            }
        }
        __syncthreads();
    }
#pragma unroll
    for (int i = 0; i < 8; i++) {
        size_t row = (size_t)(bm + ty * 8 + i);
        __half* rp = g_bch + row * 256;
        float v[8];
        unpack2(acc[i][0], v[0], v[1]); unpack2(acc[i][1], v[2], v[3]);   // b cols
        unpack2(acc[i][2], v[4], v[5]); unpack2(acc[i][3], v[6], v[7]);   // c cols
        __half h[8], l[8];
#pragma unroll
        for (int j = 0; j < 8; j++) {
            h[j] = __float2half_rn(v[j]);
            l[j] = __float2half_rn((v[j] - __half2float(h[j])) * 2048.0f);
        }
        *(__half2*)(rp + tx * 4)           = __halves2half2(h[0], h[1]);
        *(__half2*)(rp + tx * 4 + 2)       = __halves2half2(h[2], h[3]);
        *(__half2*)(rp + 64 + tx * 4)      = __halves2half2(l[0], l[1]);
        *(__half2*)(rp + 64 + tx * 4 + 2)  = __halves2half2(l[2], l[3]);
        *(__half2*)(rp + 128 + tx * 4)     = __halves2half2(h[4], h[5]);
        *(__half2*)(rp + 128 + tx * 4 + 2) = __halves2half2(h[6], h[7]);
        *(__half2*)(rp + 192 + tx * 4)     = __halves2half2(l[4], l[5]);
        *(__half2*)(rp + 192 + tx * 4 + 2) = __halves2half2(l[6], l[7]);
    }
}

// ---------- d projection (tf32 mma.sync), epilogue stores fp16 d^T ----------
__global__ void __launch_bounds__(256) dproj(const float* __restrict__ X,
                                             const float* __restrict__ Wd) {
    __shared__ uint32 Xs[128 * 20];
    __shared__ uint32 Wt[128 * 17];

    int tid = threadIdx.x;
    int lane = tid & 31, w = tid >> 5;
    int g = lane >> 2, q = lane & 3;
    int bm = blockIdx.x * 128, bn = blockIdx.y * 128;
    int mw = (w & 3) * 32, nw = (w >> 2) * 64;

    float4 acc[2][8];
#pragma unroll
    for (int i = 0; i < 2; i++)
#pragma unroll
        for (int j = 0; j < 8; j++) acc[i][j] = make_float4(0.f, 0.f, 0.f, 0.f);

    for (int kk = 0; kk < CDIM; kk += 16) {
        {
            int m = tid >> 1;
#pragma unroll
            for (int j = 0; j < 2; j++) {
                int k = (tid & 1) * 8 + j * 4;
                float4 v = *(const float4*)(X + (size_t)(bm + m) * CDIM + kk + k);
                uint4 u = make_uint4(f2tf(v.x), f2tf(v.y), f2tf(v.z), f2tf(v.w));
                *(uint4*)(Xs + m * 20 + k) = u;
            }
        }
        {
            int k = tid >> 4;
            int n0 = (tid & 15) * 4;
#pragma unroll
            for (int j = 0; j < 2; j++) {
                int n = n0 + j * 64;
                float4 v = *(const float4*)(Wd + (size_t)(kk + k) * CDIM + bn + n);
                Wt[(n + 0) * 17 + k] = f2tf(v.x);
                Wt[(n + 1) * 17 + k] = f2tf(v.y);
                Wt[(n + 2) * 17 + k] = f2tf(v.z);
                Wt[(n + 3) * 17 + k] = f2tf(v.w);
            }
        }
        __syncthreads();
#pragma unroll
        for (int ks = 0; ks < 2; ks++) {
#pragma unroll
            for (int mt = 0; mt < 2; mt++) {
                int ar = (mw + mt * 16 + g) * 20 + ks * 8 + q;
                uint32 a0 = Xs[ar], a1 = Xs[ar + 8 * 20];
                uint32 a2 = Xs[ar + 4], a3 = Xs[ar + 8 * 20 + 4];
#pragma unroll
                for (int nt = 0; nt < 8; nt++) {
                    int br = (nw + nt * 8 + g) * 17 + ks * 8 + q;
                    mma8(acc[mt][nt], a0, a1, a2, a3, Wt[br], Wt[br + 4]);
                }
            }
        }
        __syncthreads();
    }
    // epilogue: d^T fp16
#pragma unroll
    for (int mt = 0; mt < 2; mt++) {
        int r0g = bm + mw + mt * 16 + g;
        int batch = r0g >> 12, key = r0g & 4095;
#pragma unroll
        for (int nt = 0; nt < 8; nt++) {
            int col = bn + nw + nt * 8 + 2 * q;
            __half* base = g_dT + ((size_t)batch * CDIM + col) * HW;
            base[key]          = __float2half_rn(acc[mt][nt].x);
            base[HW + key]     = __float2half_rn(acc[mt][nt].y);
            base[key + 8]      = __float2half_rn(acc[mt][nt].z);
            base[HW + key + 8] = __float2half_rn(acc[mt][nt].w);
        }
    }
}

// ---------- fused flash attention, fp16 mma + ldmatrix ----------
#define CS_H   (64 * 136)
#define BS_H   (128 * 136)
#define PS_H   (64 * 136)
#define DS_H   (512 * 72)
#define SMEM_FLASH ((CS_H + BS_H + PS_H + DS_H) * 2 + 2 * 4 * 64 * 4)

__global__ void __launch_bounds__(512, 1) flash16(const float* __restrict__ x,
                                                  const float* __restrict__ gamma,
                                                  float* __restrict__ out) {
    extern __shared__ char sm[];
    __half* Cs = (__half*)sm;
    __half* Bs = Cs + CS_H;
    __half* Ps = Bs + BS_H;
    __half* Ds = Ps + PS_H;
    float* m_part = (float*)(Ds + DS_H);    // [4][64]
    float* l_part = m_part + 256;           // [4][64]

    const uint32 smb  = smem_u32(sm);
    const uint32 cs_b = smb;
    const uint32 bs_b = smb + CS_H * 2;
    const uint32 ps_b = bs_b + BS_H * 2;
    const uint32 ds_b = ps_b + PS_H * 2;

    const int tid = threadIdx.x;
    const int wid = tid >> 5, lane = tid & 31;
    const int g = lane >> 2, q = lane & 3;
    const int qg = wid & 3;          // q-group: rows qg*16..+15
    const int kq = wid >> 2;         // S: key-quarter (32k) / PV: f-quarter (128f)
    const int t15 = lane & 15;
    const int qb = blockIdx.x * 64;
    const int bz = blockIdx.y;
    const int rowbase = bz * HW;

    // ---- load Cs (ch|cl' = halves [128:256) of g_bch) ----
    {
        int r = tid >> 3, c = tid & 7;
        const uint4* src = (const uint4*)(g_bch + (size_t)(rowbase + qb + r) * 256 + 128);
        *(uint4*)(Cs + r * 136 + c * 8)       = src[c];
        *(uint4*)(Cs + r * 136 + (c + 8) * 8) = src[c + 8];
    }

    float4 oacc[16];
#pragma unroll
    for (int i = 0; i < 16; i++) oacc[i] = make_float4(0.f, 0.f, 0.f, 0.f);
    float mrun0 = -1e30f, mrun1 = -1e30f;
    float lrun0 = 0.f, lrun1 = 0.f;

    // ldmatrix base addresses
    const uint32 aCh = cs_b + (uint32)((qg * 16 + t15) * 272 + ((lane >> 4) & 1) * 16);
    const uint32 bBh = bs_b + (uint32)((kq * 32 + (lane & 7)) * 272 + ((lane >> 3) & 1) * 16);
    // PV B fragment: m0=(n0-7,k0-7) m1=(n0-7,k8-15) m2=(n8-15,k0-7) m3=(n8-15,k8-15)
    const uint32 dRowOff = (uint32)((kq * 128 + (lane & 7) + ((lane >> 4) & 1) * 8) * 144
                                    + ((lane >> 3) & 1) * 16);
    const int r0row = qg * 16 + g;

    for (int kt = 0; kt < HW; kt += 128) {
        // ---- load Bs tile [128 keys][bh|bl'] ----
        {
            int r = tid >> 2, c0 = tid & 3;
            const uint4* src = (const uint4*)(g_bch + (size_t)(rowbase + kt + r) * 256);
            __half* dst = Bs + r * 136;
#pragma unroll
            for (int j = 0; j < 4; j++)
                *(uint4*)(dst + (c0 + j * 4) * 8) = src[c0 + j * 4];
        }
        __syncthreads();

        // ---- S phase: warp = 16q x 32k, scaled fp16 split ----
        float4 skeep[4];
#pragma unroll
        for (int nt = 0; nt < 4; nt++) {
            float4 hi = make_float4(0.f, 0.f, 0.f, 0.f);
            float4 lo = make_float4(0.f, 0.f, 0.f, 0.f);
            uint32 bb = bBh + (uint32)(nt * 8 * 272);
#pragma unroll
            for (int ec = 0; ec < 4; ec++) {
                uint32 a0, a1, a2, a3, c0, c1, c2, c3, bh0, bh1, bl0, bl1;
                ldsm4(a0, a1, a2, a3, aCh + ec * 32);
                ldsm4(c0, c1, c2, c3, aCh + ec * 32 + 128);
                ldsm2(bh0, bh1, bb + ec * 32);
                ldsm2(bl0, bl1, bb + ec * 32 + 128);
                mma16(hi, a0, a1, a2, a3, bh0, bh1);
                mma16(lo, a0, a1, a2, a3, bl0, bl1);
                mma16(lo, c0, c1, c2, c3, bh0, bh1);
            }
            const float K = 1.0f / 2048.0f;
            skeep[nt] = make_float4(hi.x + lo.x * K, hi.y + lo.y * K,
                                    hi.z + lo.z * K, hi.w + lo.w * K);
        }

        // ---- fragment softmax stats ----
        float mx0 = skeep[0].x, mx1 = skeep[0].z;
#pragma unroll
        for (int nt = 0; nt < 4; nt++) {
            mx0 = fmaxf(mx0, fmaxf(skeep[nt].x, skeep[nt].y));
            mx1 = fmaxf(mx1, fmaxf(skeep[nt].z, skeep[nt].w));
        }
        mx0 = fmaxf(mx0, __shfl_xor_sync(0xffffffffu, mx0, 1));
        mx0 = fmaxf(mx0, __shfl_xor_sync(0xffffffffu, mx0, 2));
        mx1 = fmaxf(mx1, __shfl_xor_sync(0xffffffffu, mx1, 1));
        mx1 = fmaxf(mx1, __shfl_xor_sync(0xffffffffu, mx1, 2));
        if (q == 0) {
            m_part[kq * 64 + r0row]     = mx0;
            m_part[kq * 64 + r0row + 8] = mx1;
        }
        __syncthreads();

        float mt0 = fmaxf(fmaxf(m_part[r0row], m_part[64 + r0row]),
                          fmaxf(m_part[128 + r0row], m_part[192 + r0row]));
        float mt1 = fmaxf(fmaxf(m_part[r0row + 8], m_part[64 + r0row + 8]),
                          fmaxf(m_part[128 + r0row + 8], m_part[192 + r0row + 8]));
        float mn0 = fmaxf(mrun0, mt0), mn1 = fmaxf(mrun1, mt1);
        float sc0 = __expf(mrun0 - mn0), sc1 = __expf(mrun1 - mn1);
        mrun0 = mn0; mrun1 = mn1;

        float ls0 = 0.f, ls1 = 0.f;
#pragma unroll
        for (int nt = 0; nt < 4; nt++) {
            float px = __expf(skeep[nt].x - mn0), py = __expf(skeep[nt].y - mn0);
            float pz = __expf(skeep[nt].z - mn1), pw = __expf(skeep[nt].w - mn1);
            ls0 += px + py; ls1 += pz + pw;
            int col = kq * 32 + nt * 8 + 2 * q;
            *(__half2*)(Ps + r0row * 136 + col)       = __floats2half2_rn(px, py);
            *(__half2*)(Ps + (r0row + 8) * 136 + col) = __floats2half2_rn(pz, pw);
        }
        ls0 += __shfl_xor_sync(0xffffffffu, ls0, 1);
        ls0 += __shfl_xor_sync(0xffffffffu, ls0, 2);
        ls1 += __shfl_xor_sync(0xffffffffu, ls1, 1);
        ls1 += __shfl_xor_sync(0xffffffffu, ls1, 2);
        if (q == 0) {
            l_part[kq * 64 + r0row]     = ls0;
            l_part[kq * 64 + r0row + 8] = ls1;
        }
        // rescale O
#pragma unroll
        for (int nt = 0; nt < 16; nt++) {
            oacc[nt].x *= sc0; oacc[nt].y *= sc0;
            oacc[nt].z *= sc1; oacc[nt].w *= sc1;
        }
        __syncthreads();
        lrun0 = lrun0 * sc0 + (l_part[r0row] + l_part[64 + r0row]
                             + l_part[128 + r0row] + l_part[192 + r0row]);
        lrun1 = lrun1 * sc1 + (l_part[r0row + 8] + l_part[64 + r0row + 8]
                             + l_part[128 + r0row + 8] + l_part[192 + r0row + 8]);

        // ---- PV: 2 key-halves of 64 ----
#pragma unroll
        for (int kh = 0; kh < 2; kh++) {
            {
                const uint4* src = (const uint4*)(g_dT + ((size_t)(bz * CDIM + tid)) * HW
                                                  + kt + kh * 64);
                __half* dst = Ds + tid * 72;
#pragma unroll
                for (int i = 0; i < 8; i++)
                    *(uint4*)(dst + i * 8) = src[i];
            }
            __syncthreads();
#pragma unroll
            for (int kc = 0; kc < 4; kc++) {
                uint32 a0, a1, a2, a3;
                ldsm4(a0, a1, a2, a3,
                      ps_b + (uint32)((qg * 16 + t15) * 272 + (kh * 64 + kc * 16) * 2
                                      + ((lane >> 4) & 1) * 16));
#pragma unroll
                for (int ftp = 0; ftp < 8; ftp++) {
                    uint32 b0, b1, b2, b3;
                    ldsm4(b0, b1, b2, b3,
                          ds_b + dRowOff + (uint32)(ftp * 16 * 144 + kc * 32));
                    mma16(oacc[ftp * 2],     a0, a1, a2, a3, b0, b1);
                    mma16(oacc[ftp * 2 + 1], a0, a1, a2, a3, b2, b3);
                }
            }
            __syncthreads();
        }
    }

    // ---- epilogue: out = gamma * O / l + x ----
    {
        float li0 = 1.0f / lrun0, li1 = 1.0f / lrun1;
        float gam = *gamma;
        size_t row0 = (size_t)(rowbase + qb + r0row);
        size_t row1 = row0 + 8;
#pragma unroll
        for (int nt = 0; nt < 16; nt++) {
            int col = kq * 128 + nt * 8 + 2 * q;
            float2 x0 = *(const float2*)(x + row0 * CDIM + col);
            float2 x1 = *(const float2*)(x + row1 * CDIM + col);
            *(float2*)(out + row0 * CDIM + col) =
                make_float2(gam * oacc[nt].x * li0 + x0.x,
                            gam * oacc[nt].y * li0 + x0.y);
            *(float2*)(out + row1 * CDIM + col) =
                make_float2(gam * oacc[nt].z * li1 + x1.x,
                            gam * oacc[nt].w * li1 + x1.y);
        }
    }
}

// ---------- launch ----------
extern "C" void kernel_launch(void* const* d_in, const int* in_sizes, int n_in,
                              void* d_out, int out_size) {
    const float* x     = (const float*)d_in[0];
    const float* Wb    = (const float*)d_in[1];
    const float* Wc    = (const float*)d_in[2];
    const float* Wd    = (const float*)d_in[3];
    const float* gamma = (const float*)d_in[4];
    float* out = (float*)d_out;

    pack_wbc<<<128, 256>>>(Wb, Wc);
    proj_bc<<<dim3(MROWS / 128, 1), 256>>>(x);
    dproj<<<dim3(MROWS / 128, CDIM / 128), 256>>>(x, Wd);

    cudaFuncSetAttribute(flash16, cudaFuncAttributeMaxDynamicSharedMemorySize,
                         (int)SMEM_FLASH);
    flash16<<<dim3(HW / 64, BATCH), 512, SMEM_FLASH>>>(x, gamma, out);
}

// round 6
// speedup vs baseline: 4.0758x; 1.0173x over previous
#include <cuda_runtime.h>
#include <cuda_fp16.h>

typedef unsigned long long u64;
typedef unsigned int uint32;
#define DEV __device__ __forceinline__

// ---------- packed fp32x2 helpers ----------
DEV u64 pack2(float lo, float hi) {
    u64 r; asm("mov.b64 %0, {%1,%2};" : "=l"(r) : "f"(lo), "f"(hi)); return r;
}
DEV void unpack2(u64 v, float& lo, float& hi) {
    asm("mov.b64 {%0,%1}, %2;" : "=f"(lo), "=f"(hi) : "l"(v));
}
DEV u64 ffma2(u64 a, u64 b, u64 c) {
    u64 d; asm("fma.rn.f32x2 %0, %1, %2, %3;" : "=l"(d) : "l"(a), "l"(b), "l"(c)); return d;
}

// ---------- tf32 helpers (dproj) ----------
DEV uint32 f2tf(float f) {
    uint32 u; asm("cvt.rna.tf32.f32 %0, %1;" : "=r"(u) : "f"(f)); return u;
}
DEV void mma8(float4& d, uint32 a0, uint32 a1, uint32 a2, uint32 a3,
              uint32 b0, uint32 b1) {
    asm volatile("mma.sync.aligned.m16n8k8.row.col.f32.tf32.tf32.f32 "
                 "{%0,%1,%2,%3}, {%4,%5,%6,%7}, {%8,%9}, {%0,%1,%2,%3};"
                 : "+f"(d.x), "+f"(d.y), "+f"(d.z), "+f"(d.w)
                 : "r"(a0), "r"(a1), "r"(a2), "r"(a3), "r"(b0), "r"(b1));
}

// ---------- fp16 mma + ldmatrix ----------
DEV void mma16(float4& d, uint32 a0, uint32 a1, uint32 a2, uint32 a3,
               uint32 b0, uint32 b1) {
    asm volatile("mma.sync.aligned.m16n8k16.row.col.f32.f16.f16.f32 "
                 "{%0,%1,%2,%3}, {%4,%5,%6,%7}, {%8,%9}, {%0,%1,%2,%3};"
                 : "+f"(d.x), "+f"(d.y), "+f"(d.z), "+f"(d.w)
                 : "r"(a0), "r"(a1), "r"(a2), "r"(a3), "r"(b0), "r"(b1));
}
DEV void ldsm4(uint32& r0, uint32& r1, uint32& r2, uint32& r3, uint32 addr) {
    asm volatile("ldmatrix.sync.aligned.m8n8.x4.shared.b16 {%0,%1,%2,%3}, [%4];"
                 : "=r"(r0), "=r"(r1), "=r"(r2), "=r"(r3) : "r"(addr));
}
DEV void ldsm2(uint32& r0, uint32& r1, uint32 addr) {
    asm volatile("ldmatrix.sync.aligned.m8n8.x2.shared.b16 {%0,%1}, [%2];"
                 : "=r"(r0), "=r"(r1) : "r"(addr));
}
DEV uint32 smem_u32(const void* p) {
    uint32 a;
    asm("{ .reg .u64 t; cvta.to.shared.u64 t, %1; cvt.u32.u64 %0, t; }"
        : "=r"(a) : "l"(p));
    return a;
}

// ---------- cp.async ----------
#define CP16(dst, src) \
    asm volatile("cp.async.cg.shared.global [%0], [%1], 16;" :: "r"(dst), "l"(src))
#define CP_COMMIT() asm volatile("cp.async.commit_group;" ::: "memory")
#define CP_WAIT0() asm volatile("cp.async.wait_group 0;" ::: "memory")
#define CP_WAIT1() asm volatile("cp.async.wait_group 1;" ::: "memory")
#define CP_WAIT2() asm volatile("cp.async.wait_group 2;" ::: "memory")

#define BATCH 4
#define HW    4096
#define CDIM  512
#define CK    64
#define MROWS (BATCH*HW)

// ---------- device scratch ----------
__device__ __align__(128) float  g_wbc[CDIM * 128];
__device__ __align__(128) __half g_bch[(size_t)MROWS * 256];       // [row][bh|bl'|ch|cl']
__device__ __align__(128) __half g_dT[(size_t)BATCH * CDIM * HW];  // d^T [batch][f][key]

// ---------- pack Wb|Wc ----------
__global__ void pack_wbc(const float* __restrict__ Wb, const float* __restrict__ Wc) {
    int i = blockIdx.x * 256 + threadIdx.x;
    if (i < CDIM * CK) {
        int k = i / CK, n = i % CK;
        g_wbc[k * 128 + n]      = Wb[i];
        g_wbc[k * 128 + 64 + n] = Wc[i];
    }
}

// ---------- fp32 b,c projection; epilogue emits scaled fp16 splits ----------
__global__ void __launch_bounds__(256) proj_bc(const float* __restrict__ X) {
    __shared__ float As[8][132];
    __shared__ float Bs[8][128];

    int tid = threadIdx.x;
    int bm = blockIdx.x * 128;
    int tx = tid & 15, ty = tid >> 4;
    int lr = tid >> 1, lc = (tid & 1) * 4;
    int wr = tid >> 5, wc = (tid & 31) * 4;

    u64 acc[8][4];
#pragma unroll
    for (int i = 0; i < 8; i++)
#pragma unroll
        for (int j = 0; j < 4; j++) acc[i][j] = 0ull;

    for (int kk = 0; kk < CDIM; kk += 8) {
        float4 xv = *(const float4*)(X + (size_t)(bm + lr) * CDIM + kk + lc);
        As[lc + 0][lr] = xv.x; As[lc + 1][lr] = xv.y;
        As[lc + 2][lr] = xv.z; As[lc + 3][lr] = xv.w;
        *(float4*)(&Bs[wr][wc]) = *(const float4*)(g_wbc + (size_t)(kk + wr) * 128 + wc);
        __syncthreads();
#pragma unroll
        for (int k = 0; k < 8; k++) {
            float4 a0 = *(const float4*)(&As[k][ty * 8]);
            float4 a1 = *(const float4*)(&As[k][ty * 8 + 4]);
            float4 b0 = *(const float4*)(&Bs[k][tx * 4]);
            float4 b1 = *(const float4*)(&Bs[k][64 + tx * 4]);
            u64 bp0 = pack2(b0.x, b0.y), bp1 = pack2(b0.z, b0.w);
            u64 bp2 = pack2(b1.x, b1.y), bp3 = pack2(b1.z, b1.w);
            float am[8] = {a0.x, a0.y, a0.z, a0.w, a1.x, a1.y, a1.z, a1.w};
#pragma unroll
            for (int i = 0; i < 8; i++) {
                u64 ap = pack2(am[i], am[i]);
                acc[i][0] = ffma2(ap, bp0, acc[i][0]);
                acc[i][1] = ffma2(ap, bp1, acc[i][1]);
                acc[i][2] = ffma2(ap, bp2, acc[i][2]);
                acc[i][3] = ffma2(ap, bp3, acc[i][3]);
            }
        }
        __syncthreads();
    }
#pragma unroll
    for (int i = 0; i < 8; i++) {
        size_t row = (size_t)(bm + ty * 8 + i);
        __half* rp = g_bch + row * 256;
        float v[8];
        unpack2(acc[i][0], v[0], v[1]); unpack2(acc[i][1], v[2], v[3]);
        unpack2(acc[i][2], v[4], v[5]); unpack2(acc[i][3], v[6], v[7]);
        __half h[8], l[8];
#pragma unroll
        for (int j = 0; j < 8; j++) {
            h[j] = __float2half_rn(v[j]);
            l[j] = __float2half_rn((v[j] - __half2float(h[j])) * 2048.0f);
        }
        *(__half2*)(rp + tx * 4)           = __halves2half2(h[0], h[1]);
        *(__half2*)(rp + tx * 4 + 2)       = __halves2half2(h[2], h[3]);
        *(__half2*)(rp + 64 + tx * 4)      = __halves2half2(l[0], l[1]);
        *(__half2*)(rp + 64 + tx * 4 + 2)  = __halves2half2(l[2], l[3]);
        *(__half2*)(rp + 128 + tx * 4)     = __halves2half2(h[4], h[5]);
        *(__half2*)(rp + 128 + tx * 4 + 2) = __halves2half2(h[6], h[7]);
        *(__half2*)(rp + 192 + tx * 4)     = __halves2half2(l[4], l[5]);
        *(__half2*)(rp + 192 + tx * 4 + 2) = __halves2half2(l[6], l[7]);
    }
}

// ---------- d projection (tf32 mma.sync), epilogue stores fp16 d^T ----------
__global__ void __launch_bounds__(256) dproj(const float* __restrict__ X,
                                             const float* __restrict__ Wd) {
    __shared__ uint32 Xs[128 * 20];
    __shared__ uint32 Wt[128 * 17];

    int tid = threadIdx.x;
    int lane = tid & 31, w = tid >> 5;
    int g = lane >> 2, q = lane & 3;
    int bm = blockIdx.x * 128, bn = blockIdx.y * 128;
    int mw = (w & 3) * 32, nw = (w >> 2) * 64;

    float4 acc[2][8];
#pragma unroll
    for (int i = 0; i < 2; i++)
#pragma unroll
        for (int j = 0; j < 8; j++) acc[i][j] = make_float4(0.f, 0.f, 0.f, 0.f);

    for (int kk = 0; kk < CDIM; kk += 16) {
        {
            int m = tid >> 1;
#pragma unroll
            for (int j = 0; j < 2; j++) {
                int k = (tid & 1) * 8 + j * 4;
                float4 v = *(const float4*)(X + (size_t)(bm + m) * CDIM + kk + k);
                uint4 u = make_uint4(f2tf(v.x), f2tf(v.y), f2tf(v.z), f2tf(v.w));
                *(uint4*)(Xs + m * 20 + k) = u;
            }
        }
        {
            int k = tid >> 4;
            int n0 = (tid & 15) * 4;
#pragma unroll
            for (int j = 0; j < 2; j++) {
                int n = n0 + j * 64;
                float4 v = *(const float4*)(Wd + (size_t)(kk + k) * CDIM + bn + n);
                Wt[(n + 0) * 17 + k] = f2tf(v.x);
                Wt[(n + 1) * 17 + k] = f2tf(v.y);
                Wt[(n + 2) * 17 + k] = f2tf(v.z);
                Wt[(n + 3) * 17 + k] = f2tf(v.w);
            }
        }
        __syncthreads();
#pragma unroll
        for (int ks = 0; ks < 2; ks++) {
#pragma unroll
            for (int mt = 0; mt < 2; mt++) {
                int ar = (mw + mt * 16 + g) * 20 + ks * 8 + q;
                uint32 a0 = Xs[ar], a1 = Xs[ar + 8 * 20];
                uint32 a2 = Xs[ar + 4], a3 = Xs[ar + 8 * 20 + 4];
#pragma unroll
                for (int nt = 0; nt < 8; nt++) {
                    int br = (nw + nt * 8 + g) * 17 + ks * 8 + q;
                    mma8(acc[mt][nt], a0, a1, a2, a3, Wt[br], Wt[br + 4]);
                }
            }
        }
        __syncthreads();
    }
#pragma unroll
    for (int mt = 0; mt < 2; mt++) {
        int r0g = bm + mw + mt * 16 + g;
        int batch = r0g >> 12, key = r0g & 4095;
#pragma unroll
        for (int nt = 0; nt < 8; nt++) {
            int col = bn + nw + nt * 8 + 2 * q;
            __half* base = g_dT + ((size_t)batch * CDIM + col) * HW;
            base[key]          = __float2half_rn(acc[mt][nt].x);
            base[HW + key]     = __float2half_rn(acc[mt][nt].y);
            base[key + 8]      = __float2half_rn(acc[mt][nt].z);
            base[HW + key + 8] = __float2half_rn(acc[mt][nt].w);
        }
    }
}

// ---------- fused flash attention (pipelined, remapped PV) ----------
// smem layout (bytes from base):
//  Cs    [64][136]h                @ 0        (17408)
//  Bs x2 [128][136]h               @ 17408    (2*34816)
//  Ps    [64][136]h                @ 87040    (17408)
//  Ds x2 [512][40]h (32-key chunk) @ 104448   (2*40960)
//  m_part[4][64]f @186368  l_part[4][64]f @187392
//  sc_s[64]f @188416  l_fin[64]f @188672
#define CS_OFF   0
#define BS_OFF   17408
#define BS_BYTES 34816
#define PS_OFF   87040
#define DS_OFF   104448
#define DS_BYTES 40960
#define STAT_OFF 186368
#define SMEM_FLASH (STAT_OFF + 2560)

__global__ void __launch_bounds__(512, 1) flash16(const float* __restrict__ x,
                                                  const float* __restrict__ gamma,
                                                  float* __restrict__ out) {
    extern __shared__ char sm[];
    __half* Cs = (__half*)(sm + CS_OFF);
    __half* Ps = (__half*)(sm + PS_OFF);
    float* m_part = (float*)(sm + STAT_OFF);        // [4][64]
    float* l_part = m_part + 256;                   // [4][64]
    float* sc_s   = l_part + 256;                   // [64]
    float* l_fin  = sc_s + 64;                      // [64]

    const uint32 smb  = smem_u32(sm);
    const uint32 cs_b = smb + CS_OFF;
    const uint32 bs_b = smb + BS_OFF;
    const uint32 ps_b = smb + PS_OFF;
    const uint32 ds_b = smb + DS_OFF;

    const int tid = threadIdx.x;
    const int wid = tid >> 5, lane = tid & 31;
    const int g = lane >> 2, q = lane & 3;
    const int qg = wid & 3;          // S: q-group rows qg*16..+15
    const int kq = wid >> 2;         // S: key-quarter (32k)
    const int qsub = wid & 1;        // PV: q-half (32 rows)
    const int fgrp = wid >> 1;       // PV: f-group (64 cols)
    const int t15 = lane & 15;
    const int qb = blockIdx.x * 64;
    const int bz = blockIdx.y;
    const int rowbase = bz * HW;

    // ---- load Cs once (ch|cl) ----
    {
        int r = tid >> 3, c = tid & 7;
        const uint4* src = (const uint4*)(g_bch + (size_t)(rowbase + qb + r) * 256 + 128);
        *(uint4*)(Cs + r * 136 + c * 8)       = src[c];
        *(uint4*)(Cs + r * 136 + (c + 8) * 8) = src[c + 8];
    }

    float4 oacc[16];
#pragma unroll
    for (int i = 0; i < 16; i++) oacc[i] = make_float4(0.f, 0.f, 0.f, 0.f);
    float mrun0 = -1e30f, mrun1 = -1e30f;
    float lrun0 = 0.f, lrun1 = 0.f;

    // ldmatrix base addresses
    const uint32 aCh = cs_b + (uint32)((qg * 16 + t15) * 272 + ((lane >> 4) & 1) * 16);
    const uint32 bBh0 = bs_b + (uint32)((kq * 32 + (lane & 7)) * 272 + ((lane >> 3) & 1) * 16);
    const uint32 psA = ps_b + (uint32)((qsub * 32 + t15) * 272 + ((lane >> 4) & 1) * 16);
    const uint32 dRow = ds_b + (uint32)((fgrp * 64 + (lane & 7) + ((lane >> 4) & 1) * 8) * 80
                                        + ((lane >> 3) & 1) * 16);
    const int r0row = qg * 16 + g;            // S stat rows
    const int pvrow = qsub * 32 + g;          // PV rows (+16 for sub16=1)

    // gmem srcs for cp.async
    const __half* dsrc = g_dT + ((size_t)(bz * CDIM + tid)) * HW;
    const uint32 dsDst = ds_b + (uint32)(tid * 80);
    const int bsR = tid >> 2, bsC = tid & 3;
    const uint32 bsDst = bs_b + (uint32)(bsR * 272 + bsC * 16);

    // prefetch Bs tile 0
    {
        const __half* src = g_bch + (size_t)(rowbase + bsR) * 256 + bsC * 8;
#pragma unroll
        for (int j = 0; j < 4; j++) CP16(bsDst + j * 64, src + j * 32);
        CP_COMMIT();
    }

    for (int t = 0; t < 32; t++) {
        const int kt = t * 128;
        const uint32 bsBuf = (uint32)((t & 1) * BS_BYTES);

        // issue Ds chunks 0,1
#pragma unroll
        for (int c = 0; c < 2; c++) {
            const __half* src = dsrc + kt + c * 32;
            uint32 dst = dsDst + (uint32)(c * DS_BYTES);
#pragma unroll
            for (int j = 0; j < 4; j++) CP16(dst + j * 16, src + j * 8);
            CP_COMMIT();
        }
        CP_WAIT2();          // Bs(t) guaranteed done
        __syncthreads();

        // ---- S phase: ec outer (A loaded once), nt inner ----
        float4 hi[4], lo[4];
#pragma unroll
        for (int i = 0; i < 4; i++) {
            hi[i] = make_float4(0.f, 0.f, 0.f, 0.f);
            lo[i] = make_float4(0.f, 0.f, 0.f, 0.f);
        }
        const uint32 bB = bBh0 + bsBuf;
#pragma unroll
        for (int ec = 0; ec < 4; ec++) {
            uint32 ah0, ah1, ah2, ah3, al0, al1, al2, al3;
            ldsm4(ah0, ah1, ah2, ah3, aCh + ec * 32);
            ldsm4(al0, al1, al2, al3, aCh + ec * 32 + 128);
#pragma unroll
            for (int nt = 0; nt < 4; nt++) {
                uint32 bh0, bh1, bl0, bl1;
                ldsm2(bh0, bh1, bB + nt * 2176 + ec * 32);
                ldsm2(bl0, bl1, bB + nt * 2176 + ec * 32 + 128);
                mma16(hi[nt], ah0, ah1, ah2, ah3, bh0, bh1);
                mma16(lo[nt], ah0, ah1, ah2, ah3, bl0, bl1);
                mma16(lo[nt], al0, al1, al2, al3, bh0, bh1);
            }
        }
        const float K = 1.0f / 2048.0f;
        float4 skeep[4];
#pragma unroll
        for (int nt = 0; nt < 4; nt++)
            skeep[nt] = make_float4(hi[nt].x + lo[nt].x * K, hi[nt].y + lo[nt].y * K,
                                    hi[nt].z + lo[nt].z * K, hi[nt].w + lo[nt].w * K);

        // ---- softmax partials ----
        float mx0 = skeep[0].x, mx1 = skeep[0].z;
#pragma unroll
        for (int nt = 0; nt < 4; nt++) {
            mx0 = fmaxf(mx0, fmaxf(skeep[nt].x, skeep[nt].y));
            mx1 = fmaxf(mx1, fmaxf(skeep[nt].z, skeep[nt].w));
        }
        mx0 = fmaxf(mx0, __shfl_xor_sync(0xffffffffu, mx0, 1));
        mx0 = fmaxf(mx0, __shfl_xor_sync(0xffffffffu, mx0, 2));
        mx1 = fmaxf(mx1, __shfl_xor_sync(0xffffffffu, mx1, 1));
        mx1 = fmaxf(mx1, __shfl_xor_sync(0xffffffffu, mx1, 2));
        if (q == 0) {
            m_part[kq * 64 + r0row]     = mx0;
            m_part[kq * 64 + r0row + 8] = mx1;
        }
        __syncthreads();

        float mt0 = fmaxf(fmaxf(m_part[r0row], m_part[64 + r0row]),
                          fmaxf(m_part[128 + r0row], m_part[192 + r0row]));
        float mt1 = fmaxf(fmaxf(m_part[r0row + 8], m_part[64 + r0row + 8]),
                          fmaxf(m_part[128 + r0row + 8], m_part[192 + r0row + 8]));
        float mn0 = fmaxf(mrun0, mt0), mn1 = fmaxf(mrun1, mt1);
        float sc0 = __expf(mrun0 - mn0), sc1 = __expf(mrun1 - mn1);
        mrun0 = mn0; mrun1 = mn1;

        float ls0 = 0.f, ls1 = 0.f;
#pragma unroll
        for (int nt = 0; nt < 4; nt++) {
            float px = __expf(skeep[nt].x - mn0), py = __expf(skeep[nt].y - mn0);
            float pz = __expf(skeep[nt].z - mn1), pw = __expf(skeep[nt].w - mn1);
            ls0 += px + py; ls1 += pz + pw;
            int col = kq * 32 + nt * 8 + 2 * q;
            *(__half2*)(Ps + r0row * 136 + col)       = __floats2half2_rn(px, py);
            *(__half2*)(Ps + (r0row + 8) * 136 + col) = __floats2half2_rn(pz, pw);
        }
        ls0 += __shfl_xor_sync(0xffffffffu, ls0, 1);
        ls0 += __shfl_xor_sync(0xffffffffu, ls0, 2);
        ls1 += __shfl_xor_sync(0xffffffffu, ls1, 1);
        ls1 += __shfl_xor_sync(0xffffffffu, ls1, 2);
        if (q == 0) {
            l_part[kq * 64 + r0row]     = ls0;
            l_part[kq * 64 + r0row + 8] = ls1;
            if (kq == 0) { sc_s[r0row] = sc0; sc_s[r0row + 8] = sc1; }
        }

        // prefetch next Bs tile during PV
        if (t < 31) {
            const __half* src = g_bch + (size_t)(rowbase + kt + 128 + bsR) * 256 + bsC * 8;
            uint32 dst = bsDst + (uint32)(((t + 1) & 1) * BS_BYTES);
#pragma unroll
            for (int j = 0; j < 4; j++) CP16(dst + j * 64, src + j * 32);
            CP_COMMIT();
        }
        __syncthreads();

        // ---- rescale O with smem-resident scales ----
        {
            float s0 = sc_s[pvrow], s1 = sc_s[pvrow + 8];
            float s2 = sc_s[pvrow + 16], s3 = sc_s[pvrow + 24];
#pragma unroll
            for (int nt = 0; nt < 8; nt++) {
                oacc[nt].x *= s0; oacc[nt].y *= s0;
                oacc[nt].z *= s1; oacc[nt].w *= s1;
                oacc[8 + nt].x *= s2; oacc[8 + nt].y *= s2;
                oacc[8 + nt].z *= s3; oacc[8 + nt].w *= s3;
            }
        }
        lrun0 = lrun0 * sc0 + (l_part[r0row] + l_part[64 + r0row]
                             + l_part[128 + r0row] + l_part[192 + r0row]);
        lrun1 = lrun1 * sc1 + (l_part[r0row + 8] + l_part[64 + r0row + 8]
                             + l_part[128 + r0row + 8] + l_part[192 + r0row + 8]);

        // ---- PV: 4 chunks of 32 keys, pipelined ----
#pragma unroll
        for (int c = 0; c < 4; c++) {
            if (c == 0) CP_WAIT2();
            else if (c == 1) CP_WAIT2();
            else if (c == 2) CP_WAIT1();
            else CP_WAIT0();
            __syncthreads();
            const uint32 dBuf = (uint32)((c & 1) * DS_BYTES);
#pragma unroll
            for (int kcl = 0; kcl < 2; kcl++) {
                uint32 pa0, pa1, pa2, pa3, pb0, pb1, pb2, pb3;
                uint32 pcol = (uint32)(c * 64 + kcl * 32);
                ldsm4(pa0, pa1, pa2, pa3, psA + pcol);
                ldsm4(pb0, pb1, pb2, pb3, psA + 16 * 272 + pcol);
#pragma unroll
                for (int ftp = 0; ftp < 4; ftp++) {
                    uint32 b0, b1, b2, b3;
                    ldsm4(b0, b1, b2, b3, dRow + dBuf + (uint32)(ftp * 1280 + kcl * 32));
                    mma16(oacc[ftp * 2],     pa0, pa1, pa2, pa3, b0, b1);
                    mma16(oacc[ftp * 2 + 1], pa0, pa1, pa2, pa3, b2, b3);
                    mma16(oacc[8 + ftp * 2],     pb0, pb1, pb2, pb3, b0, b1);
                    mma16(oacc[8 + ftp * 2 + 1], pb0, pb1, pb2, pb3, b2, b3);
                }
            }
            __syncthreads();
            if (c < 2) {   // issue chunk c+2 into buffer c&1
                const __half* src = dsrc + kt + (c + 2) * 32;
                uint32 dst = dsDst + dBuf;
#pragma unroll
                for (int j = 0; j < 4; j++) CP16(dst + j * 16, src + j * 8);
                CP_COMMIT();
            }
        }
    }

    // ---- publish final l, epilogue ----
    if (kq == 0 && q == 0) {
        l_fin[r0row]     = lrun0;
        l_fin[r0row + 8] = lrun1;
    }
    __syncthreads();
    {
        float li0 = 1.0f / l_fin[pvrow],      li1 = 1.0f / l_fin[pvrow + 8];
        float li2 = 1.0f / l_fin[pvrow + 16], li3 = 1.0f / l_fin[pvrow + 24];
        float gam = *gamma;
#pragma unroll
        for (int sub = 0; sub < 2; sub++) {
            size_t row0 = (size_t)(rowbase + qb + pvrow + sub * 16);
            size_t row1 = row0 + 8;
            float a0 = sub ? li2 : li0, a1 = sub ? li3 : li1;
#pragma unroll
            for (int nt = 0; nt < 8; nt++) {
                int col = fgrp * 64 + nt * 8 + 2 * q;
                float4 o = oacc[sub * 8 + nt];
                float2 x0 = *(const float2*)(x + row0 * CDIM + col);
                float2 x1 = *(const float2*)(x + row1 * CDIM + col);
                *(float2*)(out + row0 * CDIM + col) =
                    make_float2(gam * o.x * a0 + x0.x, gam * o.y * a0 + x0.y);
                *(float2*)(out + row1 * CDIM + col) =
                    make_float2(gam * o.z * a1 + x1.x, gam * o.w * a1 + x1.y);
            }
        }
    }
}

// ---------- launch ----------
extern "C" void kernel_launch(void* const* d_in, const int* in_sizes, int n_in,
                              void* d_out, int out_size) {
    const float* x     = (const float*)d_in[0];
    const float* Wb    = (const float*)d_in[1];
    const float* Wc    = (const float*)d_in[2];
    const float* Wd    = (const float*)d_in[3];
    const float* gamma = (const float*)d_in[4];
    float* out = (float*)d_out;

    pack_wbc<<<128, 256>>>(Wb, Wc);
    proj_bc<<<dim3(MROWS / 128, 1), 256>>>(x);
    dproj<<<dim3(MROWS / 128, CDIM / 128), 256>>>(x, Wd);

    cudaFuncSetAttribute(flash16, cudaFuncAttributeMaxDynamicSharedMemorySize,
                         (int)SMEM_FLASH);
    flash16<<<dim3(HW / 64, BATCH), 512, SMEM_FLASH>>>(x, gamma, out);
}